// round 5
// baseline (speedup 1.0000x reference)
#include <cuda_runtime.h>
#include <cstdint>

#define B_    8
#define C_    256
#define HW_   4096
#define W_    64
#define OC3   768
#define GRP   96
#define HEADS 64

// ------------------------- scratch (static device memory) -------------------
__device__ float g_qkv[(size_t)B_ * OC3 * HW_];
__device__ float g_agg[(size_t)B_ * OC3 * HW_];
__device__ float g_att[(size_t)B_ * 512 * HW_];
__device__ float g_kv [(size_t)B_ * HEADS * 72];

__device__ __forceinline__ const float* ms_ch(int b, int c) {
    return (c < OC3) ? (g_qkv + ((size_t)(b * OC3 + c)) * HW_)
                     : (g_agg + ((size_t)(b * OC3 + (c - OC3))) * HW_);
}

// ------------------------- packed f32x2 helpers -----------------------------
__device__ __forceinline__ unsigned long long pk2(float x, float y) {
    unsigned long long r;
    asm("mov.b64 %0, {%1, %2};" : "=l"(r) : "f"(x), "f"(y));
    return r;
}
__device__ __forceinline__ void up2(unsigned long long v, float& x, float& y) {
    asm("mov.b64 {%0, %1}, %2;" : "=f"(x), "=f"(y) : "l"(v));
}
__device__ __forceinline__ void fma2(unsigned long long& d,
                                     unsigned long long a, unsigned long long b) {
    asm("fma.rn.f32x2 %0, %1, %2, %0;" : "+l"(d) : "l"(a), "l"(b));
}
__device__ __forceinline__ void cp16(uint32_t dst, const void* src) {
    asm volatile("cp.async.ca.shared.global [%0], [%1], 16;" :: "r"(dst), "l"(src));
}
#define CP_COMMIT() asm volatile("cp.async.commit_group;" ::: "memory")
#define CP_WAIT(n)  asm volatile("cp.async.wait_group %0;" :: "n"(n) : "memory")

// ------------------------- pipelined GEMM -----------------------------------
// C[b,m,p] = sum_k A[m,k] * Bsrc[b,k,p].  A row-major [M,K] (L2-resident),
// Bsrc (B_, K, HW_) streamed via 3-stage cp.async.
// grid.x = M/128 (fastest -> L2 reuse of B), grid.y = 256 n-tiles.
// EPI: C = xres + acc*inv[m] + bias[m].
template <int KDIM, bool EPI>
__global__ __launch_bounds__(256) void gemm_pipe(
    const float* __restrict__ A, const float* __restrict__ Bm,
    float* __restrict__ Cm, const float* __restrict__ xres,
    const float* __restrict__ gamma, const float* __restrict__ beta,
    const float* __restrict__ mean, const float* __restrict__ var)
{
    constexpr int NS = KDIM / 16;
    __shared__ float As[2][16][132];
    __shared__ float Bs[3][16][128];
    __shared__ float s_inv[128];
    __shared__ float s_bias[128];

    const int M  = gridDim.x * 128;
    const int m0 = blockIdx.x * 128;
    const int n0 = blockIdx.y * 128;
    const int b  = n0 >> 12;
    const int p0 = n0 & 4095;
    const int tid = threadIdx.x;
    const int tx = tid & 15;
    const int ty = tid >> 4;

    if (EPI && tid < 128) {
        int c = m0 + tid;
        float iv = gamma[c] * rsqrtf(var[c] + 1e-6f);
        s_inv[tid]  = iv;
        s_bias[tid] = beta[c] - mean[c] * iv;
    }

    int aM[2], aC[2], bK[2], bN[2];
    uint32_t bDst[3][2];
    #pragma unroll
    for (int it = 0; it < 2; it++) {
        int lin = tid + it * 256;
        aM[it] = lin >> 2;  aC[it] = (lin & 3) * 4;
        bK[it] = lin >> 5;  bN[it] = (lin & 31) * 4;
        #pragma unroll
        for (int st = 0; st < 3; st++)
            bDst[st][it] = (uint32_t)__cvta_generic_to_shared(&Bs[st][bK[it]][bN[it]]);
    }

    const float* Bbase = Bm + (size_t)b * KDIM * HW_ + p0;

    // prologue: B stages 0,1 via cp.async; A slab 0 -> As[0]; A slab 1 -> regs
    #pragma unroll
    for (int s = 0; s < 2; s++) {
        #pragma unroll
        for (int it = 0; it < 2; it++)
            cp16(bDst[s][it], Bbase + (size_t)(s * 16 + bK[it]) * HW_ + bN[it]);
        CP_COMMIT();
    }
    float4 aReg[2];
    #pragma unroll
    for (int it = 0; it < 2; it++)
        aReg[it] = *(const float4*)(A + (size_t)(m0 + aM[it]) * KDIM + aC[it]);
    #pragma unroll
    for (int it = 0; it < 2; it++) {
        As[0][aC[it] + 0][aM[it]] = aReg[it].x;
        As[0][aC[it] + 1][aM[it]] = aReg[it].y;
        As[0][aC[it] + 2][aM[it]] = aReg[it].z;
        As[0][aC[it] + 3][aM[it]] = aReg[it].w;
    }
    #pragma unroll
    for (int it = 0; it < 2; it++)
        aReg[it] = *(const float4*)(A + (size_t)(m0 + aM[it]) * KDIM + 16 + aC[it]);

    unsigned long long acc2[8][4];
    #pragma unroll
    for (int i = 0; i < 8; i++)
        #pragma unroll
        for (int j = 0; j < 4; j++) acc2[i][j] = 0ull;

    for (int s = 0; s < NS; s++) {
        if (s == NS - 1) CP_WAIT(0); else CP_WAIT(1);
        __syncthreads();
        if (s + 2 < NS) {
            int st = (s + 2) % 3;
            #pragma unroll
            for (int it = 0; it < 2; it++)
                cp16(bDst[st][it],
                     Bbase + (size_t)((s + 2) * 16 + bK[it]) * HW_ + bN[it]);
            CP_COMMIT();
        }
        if (s + 1 < NS) {
            int ab = (s + 1) & 1;
            #pragma unroll
            for (int it = 0; it < 2; it++) {
                As[ab][aC[it] + 0][aM[it]] = aReg[it].x;
                As[ab][aC[it] + 1][aM[it]] = aReg[it].y;
                As[ab][aC[it] + 2][aM[it]] = aReg[it].z;
                As[ab][aC[it] + 3][aM[it]] = aReg[it].w;
            }
        }
        if (s + 2 < NS) {
            #pragma unroll
            for (int it = 0; it < 2; it++)
                aReg[it] = *(const float4*)(A + (size_t)(m0 + aM[it]) * KDIM
                                            + (s + 2) * 16 + aC[it]);
        }
        const int ab = s & 1, bb = s % 3;
        #pragma unroll
        for (int kk = 0; kk < 16; kk++) {
            float a[8];
            *(float4*)&a[0] = *(const float4*)&As[ab][kk][ty * 4];
            *(float4*)&a[4] = *(const float4*)&As[ab][kk][ty * 4 + 64];
            unsigned long long bv[4];
            const unsigned long long* bp0 = (const unsigned long long*)&Bs[bb][kk][tx * 4];
            const unsigned long long* bp1 = (const unsigned long long*)&Bs[bb][kk][tx * 4 + 64];
            bv[0] = bp0[0]; bv[1] = bp0[1]; bv[2] = bp1[0]; bv[3] = bp1[1];
            #pragma unroll
            for (int i = 0; i < 8; i++) {
                unsigned long long aa = pk2(a[i], a[i]);
                fma2(acc2[i][0], aa, bv[0]);
                fma2(acc2[i][1], aa, bv[1]);
                fma2(acc2[i][2], aa, bv[2]);
                fma2(acc2[i][3], aa, bv[3]);
            }
        }
    }

    const size_t cb = (size_t)b * M * HW_;
    #pragma unroll
    for (int i = 0; i < 8; i++) {
        int mi = ty * 4 + (i < 4 ? i : 60 + i);
        size_t rowoff = cb + (size_t)(m0 + mi) * HW_ + p0;
        float4 v0, v1;
        up2(acc2[i][0], v0.x, v0.y); up2(acc2[i][1], v0.z, v0.w);
        up2(acc2[i][2], v1.x, v1.y); up2(acc2[i][3], v1.z, v1.w);
        if (EPI) {
            float iv = s_inv[mi], bb2 = s_bias[mi];
            float4 x0 = *(const float4*)(xres + rowoff + tx * 4);
            float4 x1 = *(const float4*)(xres + rowoff + tx * 4 + 64);
            v0.x = fmaf(v0.x, iv, bb2) + x0.x;  v0.y = fmaf(v0.y, iv, bb2) + x0.y;
            v0.z = fmaf(v0.z, iv, bb2) + x0.z;  v0.w = fmaf(v0.w, iv, bb2) + x0.w;
            v1.x = fmaf(v1.x, iv, bb2) + x1.x;  v1.y = fmaf(v1.y, iv, bb2) + x1.y;
            v1.z = fmaf(v1.z, iv, bb2) + x1.z;  v1.w = fmaf(v1.w, iv, bb2) + x1.w;
        }
        *(float4*)(Cm + rowoff + tx * 4)      = v0;
        *(float4*)(Cm + rowoff + tx * 4 + 64) = v1;
    }
}

// ---------------- fused depthwise 5x5 + grouped pointwise 8x8 ---------------
__global__ __launch_bounds__(256) void dwpw_kernel(
    const float* __restrict__ w_dw, const float* __restrict__ w_pw)
{
    int blk = blockIdx.x;
    int tyi = blk & 7;
    int g   = (blk >> 3) % GRP;
    int b   = blk / (8 * GRP);
    int y0  = tyi * 8;

    __shared__ float s_in[8][12][68];
    __shared__ float s_wdw[200];
    __shared__ float s_wpw[64];

    int tid = threadIdx.x;
    if (tid < 200) s_wdw[tid] = w_dw[g * 200 + tid];
    else if (tid < 264) s_wpw[tid - 200] = w_pw[g * 64 + tid - 200];

    const float* inb = g_qkv + ((size_t)(b * OC3 + g * 8)) * HW_;
    for (int idx = tid; idx < 8 * 12 * 68; idx += 256) {
        int i   = idx / (12 * 68);
        int rem = idx - i * (12 * 68);
        int r   = rem / 68;
        int cx  = rem - r * 68;
        int y   = y0 + r - 2;
        int xx  = cx - 2;
        float v = 0.f;
        if ((unsigned)y < 64u && (unsigned)xx < 64u)
            v = inb[(size_t)i * HW_ + y * W_ + xx];
        s_in[i][r][cx] = v;
    }
    __syncthreads();

    #pragma unroll
    for (int pp = 0; pp < 2; pp++) {
        int px = tid + pp * 256;
        int yl = px >> 6;
        int x  = px & 63;
        float dwv[8];
        #pragma unroll
        for (int i = 0; i < 8; i++) {
            float s = 0.f;
            #pragma unroll
            for (int dy = 0; dy < 5; dy++)
                #pragma unroll
                for (int dx = 0; dx < 5; dx++)
                    s = fmaf(s_in[i][yl + dy][x + dx], s_wdw[i * 25 + dy * 5 + dx], s);
            dwv[i] = s;
        }
        size_t obase = ((size_t)(b * OC3 + g * 8)) * HW_ + (size_t)(y0 + yl) * W_ + x;
        #pragma unroll
        for (int o = 0; o < 8; o++) {
            float s = 0.f;
            #pragma unroll
            for (int i = 0; i < 8; i++) s = fmaf(s_wpw[o * 8 + i], dwv[i], s);
            g_agg[obase + (size_t)o * HW_] = s;
        }
    }
}

// ---------------- kv = sum_n relu(k)[d] * [v,1][e]  per (b,head) ------------
__global__ __launch_bounds__(256) void kv_kernel()
{
    int blk = blockIdx.x;
    int b = blk >> 6;
    int h = blk & 63;
    const float* kb = ms_ch(b, h * 24 + 8);

    float acc[8][9];
    #pragma unroll
    for (int d = 0; d < 8; d++)
        #pragma unroll
        for (int e = 0; e < 9; e++) acc[d][e] = 0.f;

    int tid = threadIdx.x;
    for (int p = tid; p < HW_; p += 256) {
        float kk[8], vv[8];
        #pragma unroll
        for (int d = 0; d < 8; d++) kk[d] = fmaxf(kb[(size_t)d * HW_ + p], 0.f);
        #pragma unroll
        for (int d = 0; d < 8; d++) vv[d] = kb[(size_t)(8 + d) * HW_ + p];
        #pragma unroll
        for (int d = 0; d < 8; d++) {
            #pragma unroll
            for (int e = 0; e < 8; e++) acc[d][e] = fmaf(kk[d], vv[e], acc[d][e]);
            acc[d][8] += kk[d];
        }
    }

    #pragma unroll
    for (int d = 0; d < 8; d++)
        #pragma unroll
        for (int e = 0; e < 9; e++)
            #pragma unroll
            for (int off = 16; off > 0; off >>= 1)
                acc[d][e] += __shfl_down_sync(0xffffffffu, acc[d][e], off);

    __shared__ float red[8][72];
    int warp = tid >> 5, lane = tid & 31;
    if (lane == 0) {
        #pragma unroll
        for (int d = 0; d < 8; d++)
            #pragma unroll
            for (int e = 0; e < 9; e++) red[warp][d * 9 + e] = acc[d][e];
    }
    __syncthreads();
    if (tid < 72) {
        float s = 0.f;
        #pragma unroll
        for (int w = 0; w < 8; w++) s += red[w][tid];
        g_kv[(size_t)blk * 72 + tid] = s;
    }
}

// ---------------- att = (q @ kv)[:8] / ((q @ kv)[8] + eps) ------------------
__global__ __launch_bounds__(256) void att_kernel()
{
    int blk = blockIdx.x;
    int pt = blk & 15;
    int h  = (blk >> 4) & 63;
    int b  = blk >> 10;

    __shared__ float kv[72];
    int tid = threadIdx.x;
    if (tid < 72) kv[tid] = g_kv[(size_t)(b * HEADS + h) * 72 + tid];
    __syncthreads();

    int p = pt * 256 + tid;
    const float* qp = ms_ch(b, h * 24);
    float q[8];
    #pragma unroll
    for (int d = 0; d < 8; d++) q[d] = fmaxf(qp[(size_t)d * HW_ + p], 0.f);

    float num[9];
    #pragma unroll
    for (int e = 0; e < 9; e++) {
        float s = 0.f;
        #pragma unroll
        for (int d = 0; d < 8; d++) s = fmaf(q[d], kv[d * 9 + e], s);
        num[e] = s;
    }
    float r = 1.f / (num[8] + 1e-15f);
    float* op = g_att + ((size_t)(b * 512 + h * 8)) * HW_ + p;
    #pragma unroll
    for (int e = 0; e < 8; e++) op[(size_t)e * HW_] = num[e] * r;
}

// ---------------------------------------------------------------------------
extern "C" void kernel_launch(void* const* d_in, const int* in_sizes, int n_in,
                              void* d_out, int out_size)
{
    const float* x      = (const float*)d_in[0];
    const float* w_qkv  = (const float*)d_in[1];
    const float* w_dw   = (const float*)d_in[2];
    const float* w_pw   = (const float*)d_in[3];
    const float* w_proj = (const float*)d_in[4];
    const float* gamma  = (const float*)d_in[5];
    const float* beta   = (const float*)d_in[6];
    const float* mean   = (const float*)d_in[7];
    const float* var    = (const float*)d_in[8];
    float* out = (float*)d_out;

    float *p_qkv, *p_att;
    cudaGetSymbolAddress((void**)&p_qkv, g_qkv);
    cudaGetSymbolAddress((void**)&p_att, g_att);

    // 1) qkv = w_qkv @ x   (M=768, K=256), cp.async pipelined
    gemm_pipe<256, false><<<dim3(6, 256), 256>>>(
        w_qkv, x, p_qkv, nullptr, nullptr, nullptr, nullptr, nullptr);
    // 2) depthwise 5x5 + grouped pointwise -> agg
    dwpw_kernel<<<6144, 256>>>(w_dw, w_pw);
    // 3) per-head kv reduction
    kv_kernel<<<512, 256>>>();
    // 4) attention output
    att_kernel<<<8192, 256>>>();
    // 5) proj GEMM + BN + residual (M=256, K=512), cp.async pipelined
    gemm_pipe<512, true><<<dim3(2, 256), 256>>>(
        w_proj, p_att, out, x, gamma, beta, mean, var);
}

// round 6
// speedup vs baseline: 1.1386x; 1.1386x over previous
#include <cuda_runtime.h>
#include <cstdint>

#define B_    8
#define C_    256
#define HW_   4096
#define W_    64
#define OC3   768
#define GRP   96
#define HEADS 64

// ------------------------- scratch (static device memory) -------------------
__device__ float g_qkv[(size_t)B_ * OC3 * HW_];
__device__ float g_agg[(size_t)B_ * OC3 * HW_];
__device__ float g_kv [(size_t)B_ * HEADS * 72];

__device__ __forceinline__ const float* ms_ch(int b, int c) {
    return (c < OC3) ? (g_qkv + ((size_t)(b * OC3 + c)) * HW_)
                     : (g_agg + ((size_t)(b * OC3 + (c - OC3))) * HW_);
}

// ------------------------- packed f32x2 helpers -----------------------------
__device__ __forceinline__ unsigned long long pk2(float x, float y) {
    unsigned long long r;
    asm("mov.b64 %0, {%1, %2};" : "=l"(r) : "f"(x), "f"(y));
    return r;
}
__device__ __forceinline__ void up2(unsigned long long v, float& x, float& y) {
    asm("mov.b64 {%0, %1}, %2;" : "=f"(x), "=f"(y) : "l"(v));
}
__device__ __forceinline__ void fma2(unsigned long long& d,
                                     unsigned long long a, unsigned long long b) {
    asm("fma.rn.f32x2 %0, %1, %2, %0;" : "+l"(d) : "l"(a), "l"(b));
}

// ------------------------- GEMM: qkv = w_qkv @ x ----------------------------
// C[b,m,p] = sum_k A[m,k] * Bsrc[b,k,p].  A row-major [M,K], Bsrc (B_,K,HW_).
// grid.x = 256 n-tiles, grid.y = M/128.
template <int KDIM>
__global__ __launch_bounds__(256, 3) void gemm_kernel(
    const float* __restrict__ A, const float* __restrict__ Bm,
    float* __restrict__ Cm)
{
    __shared__ float As[16][132];
    __shared__ float Bs[16][128];

    const int M  = gridDim.y * 128;
    const int m0 = blockIdx.y * 128;
    const int n0 = blockIdx.x * 128;
    const int b  = n0 >> 12;
    const int p0 = n0 & 4095;
    const int tid = threadIdx.x;
    const int tx = tid & 15;
    const int ty = tid >> 4;

    unsigned long long acc2[8][4];
    #pragma unroll
    for (int i = 0; i < 8; i++)
        #pragma unroll
        for (int j = 0; j < 4; j++) acc2[i][j] = 0ull;

    const float* Bbase = Bm + (size_t)b * KDIM * HW_ + p0;

    for (int k0 = 0; k0 < KDIM; k0 += 16) {
        #pragma unroll
        for (int it = 0; it < 2; it++) {
            int lin = tid + it * 256;
            int m  = lin >> 2;
            int c4 = (lin & 3) * 4;
            float4 v = *(const float4*)(A + (size_t)(m0 + m) * KDIM + k0 + c4);
            As[c4 + 0][m] = v.x; As[c4 + 1][m] = v.y;
            As[c4 + 2][m] = v.z; As[c4 + 3][m] = v.w;
        }
        #pragma unroll
        for (int it = 0; it < 2; it++) {
            int lin = tid + it * 256;
            int kr = lin >> 5;
            int nj = (lin & 31) * 4;
            float4 v = *(const float4*)(Bbase + (size_t)(k0 + kr) * HW_ + nj);
            *(float4*)&Bs[kr][nj] = v;
        }
        __syncthreads();
        #pragma unroll
        for (int kk = 0; kk < 16; kk++) {
            float a[8];
            *(float4*)&a[0] = *(const float4*)&As[kk][ty * 4];
            *(float4*)&a[4] = *(const float4*)&As[kk][ty * 4 + 64];
            unsigned long long bv[4];
            const unsigned long long* bp0 = (const unsigned long long*)&Bs[kk][tx * 4];
            const unsigned long long* bp1 = (const unsigned long long*)&Bs[kk][tx * 4 + 64];
            bv[0] = bp0[0]; bv[1] = bp0[1]; bv[2] = bp1[0]; bv[3] = bp1[1];
            #pragma unroll
            for (int i = 0; i < 8; i++) {
                unsigned long long aa = pk2(a[i], a[i]);
                fma2(acc2[i][0], aa, bv[0]);
                fma2(acc2[i][1], aa, bv[1]);
                fma2(acc2[i][2], aa, bv[2]);
                fma2(acc2[i][3], aa, bv[3]);
            }
        }
        __syncthreads();
    }

    const size_t cb = (size_t)b * M * HW_;
    #pragma unroll
    for (int i = 0; i < 8; i++) {
        int mi = ty * 4 + (i < 4 ? i : 60 + i);
        size_t rowoff = cb + (size_t)(m0 + mi) * HW_ + p0;
        float4 v0, v1;
        up2(acc2[i][0], v0.x, v0.y); up2(acc2[i][1], v0.z, v0.w);
        up2(acc2[i][2], v1.x, v1.y); up2(acc2[i][3], v1.z, v1.w);
        *(float4*)(Cm + rowoff + tx * 4)      = v0;
        *(float4*)(Cm + rowoff + tx * 4 + 64) = v1;
    }
}

// ---------------- fused proj GEMM: out = x + BN(w_proj @ att) ---------------
// att built on the fly per 16x128 B-tile from q + kv.
__global__ __launch_bounds__(256, 3) void proj_kernel(
    const float* __restrict__ A, float* __restrict__ Cm,
    const float* __restrict__ xres,
    const float* __restrict__ gamma, const float* __restrict__ beta,
    const float* __restrict__ mean, const float* __restrict__ var)
{
    __shared__ float As[16][132];
    __shared__ float Bs[16][128];
    __shared__ float kvs[HEADS * 72];
    __shared__ float s_inv[128];
    __shared__ float s_bias[128];

    const int m0 = blockIdx.y * 128;
    const int n0 = blockIdx.x * 128;
    const int b  = n0 >> 12;
    const int p0 = n0 & 4095;
    const int tid = threadIdx.x;
    const int tx = tid & 15;
    const int ty = tid >> 4;

    if (tid < 128) {
        int c = m0 + tid;
        float iv = gamma[c] * rsqrtf(var[c] + 1e-6f);
        s_inv[tid]  = iv;
        s_bias[tid] = beta[c] - mean[c] * iv;
    }
    for (int i = tid; i < HEADS * 72; i += 256)
        kvs[i] = g_kv[(size_t)b * HEADS * 72 + i];
    __syncthreads();

    unsigned long long acc2[8][4];
    #pragma unroll
    for (int i = 0; i < 8; i++)
        #pragma unroll
        for (int j = 0; j < 4; j++) acc2[i][j] = 0ull;

    const int hh = tid >> 7;
    const int px = tid & 127;

    for (int k0 = 0; k0 < 512; k0 += 16) {
        #pragma unroll
        for (int it = 0; it < 2; it++) {
            int lin = tid + it * 256;
            int m  = lin >> 2;
            int c4 = (lin & 3) * 4;
            float4 v = *(const float4*)(A + (size_t)(m0 + m) * 512 + k0 + c4);
            As[c4 + 0][m] = v.x; As[c4 + 1][m] = v.y;
            As[c4 + 2][m] = v.z; As[c4 + 3][m] = v.w;
        }
        {
            int h = (k0 >> 3) + hh;
            const float* qb = ms_ch(b, h * 24);
            const float* kvp = &kvs[h * 72];
            float q[8];
            #pragma unroll
            for (int d = 0; d < 8; d++)
                q[d] = fmaxf(qb[(size_t)d * HW_ + p0 + px], 0.f);
            float den = 0.f;
            #pragma unroll
            for (int d = 0; d < 8; d++) den = fmaf(q[d], kvp[d * 9 + 8], den);
            float r = 1.f / (den + 1e-15f);
            #pragma unroll
            for (int e = 0; e < 8; e++) {
                float s = 0.f;
                #pragma unroll
                for (int d = 0; d < 8; d++) s = fmaf(q[d], kvp[d * 9 + e], s);
                Bs[hh * 8 + e][px] = s * r;
            }
        }
        __syncthreads();
        #pragma unroll
        for (int kk = 0; kk < 16; kk++) {
            float a[8];
            *(float4*)&a[0] = *(const float4*)&As[kk][ty * 4];
            *(float4*)&a[4] = *(const float4*)&As[kk][ty * 4 + 64];
            unsigned long long bv[4];
            const unsigned long long* bp0 = (const unsigned long long*)&Bs[kk][tx * 4];
            const unsigned long long* bp1 = (const unsigned long long*)&Bs[kk][tx * 4 + 64];
            bv[0] = bp0[0]; bv[1] = bp0[1]; bv[2] = bp1[0]; bv[3] = bp1[1];
            #pragma unroll
            for (int i = 0; i < 8; i++) {
                unsigned long long aa = pk2(a[i], a[i]);
                fma2(acc2[i][0], aa, bv[0]);
                fma2(acc2[i][1], aa, bv[1]);
                fma2(acc2[i][2], aa, bv[2]);
                fma2(acc2[i][3], aa, bv[3]);
            }
        }
        __syncthreads();
    }

    const size_t cb = (size_t)b * 256 * HW_;
    #pragma unroll
    for (int i = 0; i < 8; i++) {
        int mi = ty * 4 + (i < 4 ? i : 60 + i);
        size_t rowoff = cb + (size_t)(m0 + mi) * HW_ + p0;
        float4 v0, v1;
        up2(acc2[i][0], v0.x, v0.y); up2(acc2[i][1], v0.z, v0.w);
        up2(acc2[i][2], v1.x, v1.y); up2(acc2[i][3], v1.z, v1.w);
        float iv = s_inv[mi], bb = s_bias[mi];
        float4 x0 = *(const float4*)(xres + rowoff + tx * 4);
        float4 x1 = *(const float4*)(xres + rowoff + tx * 4 + 64);
        v0.x = fmaf(v0.x, iv, bb) + x0.x;  v0.y = fmaf(v0.y, iv, bb) + x0.y;
        v0.z = fmaf(v0.z, iv, bb) + x0.z;  v0.w = fmaf(v0.w, iv, bb) + x0.w;
        v1.x = fmaf(v1.x, iv, bb) + x1.x;  v1.y = fmaf(v1.y, iv, bb) + x1.y;
        v1.z = fmaf(v1.z, iv, bb) + x1.z;  v1.w = fmaf(v1.w, iv, bb) + x1.w;
        *(float4*)(Cm + rowoff + tx * 4)      = v0;
        *(float4*)(Cm + rowoff + tx * 4 + 64) = v1;
    }
}

// ---------------- fused depthwise 5x5 + grouped pointwise 8x8 ---------------
__global__ __launch_bounds__(256) void dwpw_kernel(
    const float* __restrict__ w_dw, const float* __restrict__ w_pw)
{
    int blk = blockIdx.x;
    int tyi = blk & 7;
    int g   = (blk >> 3) % GRP;
    int b   = blk / (8 * GRP);
    int y0  = tyi * 8;

    __shared__ float s_in[8][12][68];
    __shared__ float s_wdw[200];
    __shared__ float s_wpw[64];

    int tid = threadIdx.x;
    if (tid < 200) s_wdw[tid] = w_dw[g * 200 + tid];
    else if (tid < 264) s_wpw[tid - 200] = w_pw[g * 64 + tid - 200];

    const float* inb = g_qkv + ((size_t)(b * OC3 + g * 8)) * HW_;
    for (int idx = tid; idx < 8 * 12 * 68; idx += 256) {
        int i   = idx / (12 * 68);
        int rem = idx - i * (12 * 68);
        int r   = rem / 68;
        int cx  = rem - r * 68;
        int y   = y0 + r - 2;
        int xx  = cx - 2;
        float v = 0.f;
        if ((unsigned)y < 64u && (unsigned)xx < 64u)
            v = inb[(size_t)i * HW_ + y * W_ + xx];
        s_in[i][r][cx] = v;
    }
    __syncthreads();

    #pragma unroll
    for (int pp = 0; pp < 2; pp++) {
        int px = tid + pp * 256;
        int yl = px >> 6;
        int x  = px & 63;
        float dwv[8];
        #pragma unroll
        for (int i = 0; i < 8; i++) {
            float s = 0.f;
            #pragma unroll
            for (int dy = 0; dy < 5; dy++)
                #pragma unroll
                for (int dx = 0; dx < 5; dx++)
                    s = fmaf(s_in[i][yl + dy][x + dx], s_wdw[i * 25 + dy * 5 + dx], s);
            dwv[i] = s;
        }
        size_t obase = ((size_t)(b * OC3 + g * 8)) * HW_ + (size_t)(y0 + yl) * W_ + x;
        #pragma unroll
        for (int o = 0; o < 8; o++) {
            float s = 0.f;
            #pragma unroll
            for (int i = 0; i < 8; i++) s = fmaf(s_wpw[o * 8 + i], dwv[i], s);
            g_agg[obase + (size_t)o * HW_] = s;
        }
    }
}

// ---------------- kv = sum_n relu(k)[d] * [v,1][e]  per (b,head) ------------
__global__ __launch_bounds__(256) void kv_kernel()
{
    int blk = blockIdx.x;
    int b = blk >> 6;
    int h = blk & 63;
    const float* kb = ms_ch(b, h * 24 + 8);

    float acc[8][9];
    #pragma unroll
    for (int d = 0; d < 8; d++)
        #pragma unroll
        for (int e = 0; e < 9; e++) acc[d][e] = 0.f;

    int tid = threadIdx.x;
    for (int p = tid; p < HW_; p += 256) {
        float kk[8], vv[8];
        #pragma unroll
        for (int d = 0; d < 8; d++) kk[d] = fmaxf(kb[(size_t)d * HW_ + p], 0.f);
        #pragma unroll
        for (int d = 0; d < 8; d++) vv[d] = kb[(size_t)(8 + d) * HW_ + p];
        #pragma unroll
        for (int d = 0; d < 8; d++) {
            #pragma unroll
            for (int e = 0; e < 8; e++) acc[d][e] = fmaf(kk[d], vv[e], acc[d][e]);
            acc[d][8] += kk[d];
        }
    }

    #pragma unroll
    for (int d = 0; d < 8; d++)
        #pragma unroll
        for (int e = 0; e < 9; e++)
            #pragma unroll
            for (int off = 16; off > 0; off >>= 1)
                acc[d][e] += __shfl_down_sync(0xffffffffu, acc[d][e], off);

    __shared__ float red[8][72];
    int warp = tid >> 5, lane = tid & 31;
    if (lane == 0) {
        #pragma unroll
        for (int d = 0; d < 8; d++)
            #pragma unroll
            for (int e = 0; e < 9; e++) red[warp][d * 9 + e] = acc[d][e];
    }
    __syncthreads();
    if (tid < 72) {
        float s = 0.f;
        #pragma unroll
        for (int w = 0; w < 8; w++) s += red[w][tid];
        g_kv[(size_t)blk * 72 + tid] = s;
    }
}

// ---------------------------------------------------------------------------
extern "C" void kernel_launch(void* const* d_in, const int* in_sizes, int n_in,
                              void* d_out, int out_size)
{
    const float* x      = (const float*)d_in[0];
    const float* w_qkv  = (const float*)d_in[1];
    const float* w_dw   = (const float*)d_in[2];
    const float* w_pw   = (const float*)d_in[3];
    const float* w_proj = (const float*)d_in[4];
    const float* gamma  = (const float*)d_in[5];
    const float* beta   = (const float*)d_in[6];
    const float* mean   = (const float*)d_in[7];
    const float* var    = (const float*)d_in[8];
    float* out = (float*)d_out;

    float* p_qkv;
    cudaGetSymbolAddress((void**)&p_qkv, g_qkv);

    // 1) qkv = w_qkv @ x   (M=768, K=256)
    gemm_kernel<256><<<dim3(256, 6), 256>>>(w_qkv, x, p_qkv);
    // 2) depthwise 5x5 + grouped pointwise -> agg
    dwpw_kernel<<<6144, 256>>>(w_dw, w_pw);
    // 3) per-head kv reduction
    kv_kernel<<<512, 256>>>();
    // 4) proj GEMM with on-the-fly attention + BN + residual
    proj_kernel<<<dim3(256, 2), 256>>>(w_proj, out, x, gamma, beta, mean, var);
}

// round 9
// speedup vs baseline: 1.3672x; 1.2007x over previous
#include <cuda_runtime.h>
#include <cstdint>

#define B_    8
#define C_    256
#define HW_   4096
#define W_    64
#define OC3   768
#define GRP   96
#define HEADS 64

// ------------------------- scratch (static device memory) -------------------
__device__ float g_qkv[(size_t)B_ * OC3 * HW_];
__device__ float g_agg[(size_t)B_ * OC3 * HW_];
__device__ float g_kv [(size_t)B_ * HEADS * 72];

__device__ __forceinline__ const float* ms_ch(int b, int c) {
    return (c < OC3) ? (g_qkv + ((size_t)(b * OC3 + c)) * HW_)
                     : (g_agg + ((size_t)(b * OC3 + (c - OC3))) * HW_);
}

// ------------------------- GEMM: qkv = w_qkv @ x ----------------------------
// C[b,m,p] = sum_k A[m,k] * Bsrc[b,k,p].  A row-major [M,K], Bsrc (B_,K,HW_).
// Single-buffer smem (R2 structure, known good), fragment double-buffer in
// registers to hide LDS latency inside the kk loop.
template <int KDIM>
__global__ __launch_bounds__(256, 2) void gemm_kernel(
    const float* __restrict__ A, const float* __restrict__ Bm,
    float* __restrict__ Cm)
{
    __shared__ float As[16][132];
    __shared__ float Bs[16][128];

    const int M  = gridDim.y * 128;
    const int m0 = blockIdx.y * 128;
    const int n0 = blockIdx.x * 128;
    const int b  = n0 >> 12;
    const int p0 = n0 & 4095;
    const int tid = threadIdx.x;
    const int tx = tid & 15;
    const int ty = tid >> 4;

    float acc[8][8];
    #pragma unroll
    for (int i = 0; i < 8; i++)
        #pragma unroll
        for (int j = 0; j < 8; j++) acc[i][j] = 0.f;

    const float* Bbase = Bm + (size_t)b * KDIM * HW_ + p0;

    for (int k0 = 0; k0 < KDIM; k0 += 16) {
        #pragma unroll
        for (int it = 0; it < 2; it++) {
            int lin = tid + it * 256;
            int m  = lin >> 2;
            int c4 = (lin & 3) * 4;
            float4 v = *(const float4*)(A + (size_t)(m0 + m) * KDIM + k0 + c4);
            As[c4 + 0][m] = v.x; As[c4 + 1][m] = v.y;
            As[c4 + 2][m] = v.z; As[c4 + 3][m] = v.w;
        }
        #pragma unroll
        for (int it = 0; it < 2; it++) {
            int lin = tid + it * 256;
            int kr = lin >> 5;
            int nj = (lin & 31) * 4;
            float4 v = *(const float4*)(Bbase + (size_t)(k0 + kr) * HW_ + nj);
            *(float4*)&Bs[kr][nj] = v;
        }
        __syncthreads();

        float af[2][8], bf[2][8];
        *(float4*)&af[0][0] = *(const float4*)&As[0][ty * 4];
        *(float4*)&af[0][4] = *(const float4*)&As[0][ty * 4 + 64];
        *(float4*)&bf[0][0] = *(const float4*)&Bs[0][tx * 4];
        *(float4*)&bf[0][4] = *(const float4*)&Bs[0][tx * 4 + 64];
        #pragma unroll
        for (int kk = 0; kk < 16; kk++) {
            const int c = kk & 1, n = c ^ 1;
            if (kk < 15) {
                *(float4*)&af[n][0] = *(const float4*)&As[kk + 1][ty * 4];
                *(float4*)&af[n][4] = *(const float4*)&As[kk + 1][ty * 4 + 64];
                *(float4*)&bf[n][0] = *(const float4*)&Bs[kk + 1][tx * 4];
                *(float4*)&bf[n][4] = *(const float4*)&Bs[kk + 1][tx * 4 + 64];
            }
            #pragma unroll
            for (int i = 0; i < 8; i++)
                #pragma unroll
                for (int j = 0; j < 8; j++)
                    acc[i][j] = fmaf(af[c][i], bf[c][j], acc[i][j]);
        }
        __syncthreads();
    }

    const size_t cb = (size_t)b * M * HW_;
    #pragma unroll
    for (int i = 0; i < 8; i++) {
        int mi = ty * 4 + (i < 4 ? i : 60 + i);
        size_t rowoff = cb + (size_t)(m0 + mi) * HW_ + p0;
        float4 v0 = make_float4(acc[i][0], acc[i][1], acc[i][2], acc[i][3]);
        float4 v1 = make_float4(acc[i][4], acc[i][5], acc[i][6], acc[i][7]);
        *(float4*)(Cm + rowoff + tx * 4)      = v0;
        *(float4*)(Cm + rowoff + tx * 4 + 64) = v1;
    }
}

// ---------------- fused proj GEMM: out = x + BN(w_proj @ att) ---------------
// R2 structure (att rows built on the fly per slab), fragment double-buffer
// in the kk loop.
__global__ __launch_bounds__(256, 2) void proj_kernel(
    const float* __restrict__ A, float* __restrict__ Cm,
    const float* __restrict__ xres,
    const float* __restrict__ gamma, const float* __restrict__ beta,
    const float* __restrict__ mean, const float* __restrict__ var)
{
    __shared__ float As[16][132];
    __shared__ float Bs[16][128];
    __shared__ float kvs[HEADS * 72];
    __shared__ float s_inv[128];
    __shared__ float s_bias[128];

    const int m0 = blockIdx.y * 128;
    const int n0 = blockIdx.x * 128;
    const int b  = n0 >> 12;
    const int p0 = n0 & 4095;
    const int tid = threadIdx.x;
    const int tx = tid & 15;
    const int ty = tid >> 4;

    if (tid < 128) {
        int c = m0 + tid;
        float iv = gamma[c] * rsqrtf(var[c] + 1e-6f);
        s_inv[tid]  = iv;
        s_bias[tid] = beta[c] - mean[c] * iv;
    }
    for (int i = tid; i < HEADS * 72; i += 256)
        kvs[i] = g_kv[(size_t)b * HEADS * 72 + i];
    __syncthreads();

    float acc[8][8];
    #pragma unroll
    for (int i = 0; i < 8; i++)
        #pragma unroll
        for (int j = 0; j < 8; j++) acc[i][j] = 0.f;

    const int hh = tid >> 7;
    const int px = tid & 127;

    for (int k0 = 0; k0 < 512; k0 += 16) {
        #pragma unroll
        for (int it = 0; it < 2; it++) {
            int lin = tid + it * 256;
            int m  = lin >> 2;
            int c4 = (lin & 3) * 4;
            float4 v = *(const float4*)(A + (size_t)(m0 + m) * 512 + k0 + c4);
            As[c4 + 0][m] = v.x; As[c4 + 1][m] = v.y;
            As[c4 + 2][m] = v.z; As[c4 + 3][m] = v.w;
        }
        {
            int h = (k0 >> 3) + hh;
            const float* qb = ms_ch(b, h * 24);
            const float* kvp = &kvs[h * 72];
            float q[8];
            #pragma unroll
            for (int d = 0; d < 8; d++)
                q[d] = fmaxf(qb[(size_t)d * HW_ + p0 + px], 0.f);
            float den = 0.f;
            #pragma unroll
            for (int d = 0; d < 8; d++) den = fmaf(q[d], kvp[d * 9 + 8], den);
            float r = 1.f / (den + 1e-15f);
            #pragma unroll
            for (int e = 0; e < 8; e++) {
                float s = 0.f;
                #pragma unroll
                for (int d = 0; d < 8; d++) s = fmaf(q[d], kvp[d * 9 + e], s);
                Bs[hh * 8 + e][px] = s * r;
            }
        }
        __syncthreads();

        float af[2][8], bf[2][8];
        *(float4*)&af[0][0] = *(const float4*)&As[0][ty * 4];
        *(float4*)&af[0][4] = *(const float4*)&As[0][ty * 4 + 64];
        *(float4*)&bf[0][0] = *(const float4*)&Bs[0][tx * 4];
        *(float4*)&bf[0][4] = *(const float4*)&Bs[0][tx * 4 + 64];
        #pragma unroll
        for (int kk = 0; kk < 16; kk++) {
            const int c = kk & 1, n = c ^ 1;
            if (kk < 15) {
                *(float4*)&af[n][0] = *(const float4*)&As[kk + 1][ty * 4];
                *(float4*)&af[n][4] = *(const float4*)&As[kk + 1][ty * 4 + 64];
                *(float4*)&bf[n][0] = *(const float4*)&Bs[kk + 1][tx * 4];
                *(float4*)&bf[n][4] = *(const float4*)&Bs[kk + 1][tx * 4 + 64];
            }
            #pragma unroll
            for (int i = 0; i < 8; i++)
                #pragma unroll
                for (int j = 0; j < 8; j++)
                    acc[i][j] = fmaf(af[c][i], bf[c][j], acc[i][j]);
        }
        __syncthreads();
    }

    const size_t cb = (size_t)b * 256 * HW_;
    #pragma unroll
    for (int i = 0; i < 8; i++) {
        int mi = ty * 4 + (i < 4 ? i : 60 + i);
        size_t rowoff = cb + (size_t)(m0 + mi) * HW_ + p0;
        float4 v0 = make_float4(acc[i][0], acc[i][1], acc[i][2], acc[i][3]);
        float4 v1 = make_float4(acc[i][4], acc[i][5], acc[i][6], acc[i][7]);
        float iv = s_inv[mi], bb = s_bias[mi];
        float4 x0 = *(const float4*)(xres + rowoff + tx * 4);
        float4 x1 = *(const float4*)(xres + rowoff + tx * 4 + 64);
        v0.x = fmaf(v0.x, iv, bb) + x0.x;  v0.y = fmaf(v0.y, iv, bb) + x0.y;
        v0.z = fmaf(v0.z, iv, bb) + x0.z;  v0.w = fmaf(v0.w, iv, bb) + x0.w;
        v1.x = fmaf(v1.x, iv, bb) + x1.x;  v1.y = fmaf(v1.y, iv, bb) + x1.y;
        v1.z = fmaf(v1.z, iv, bb) + x1.z;  v1.w = fmaf(v1.w, iv, bb) + x1.w;
        *(float4*)(Cm + rowoff + tx * 4)      = v0;
        *(float4*)(Cm + rowoff + tx * 4 + 64) = v1;
    }
}

// ---------------- fused depthwise 5x5 + grouped pointwise 8x8 ---------------
__global__ __launch_bounds__(256) void dwpw_kernel(
    const float* __restrict__ w_dw, const float* __restrict__ w_pw)
{
    int blk = blockIdx.x;
    int tyi = blk & 7;
    int g   = (blk >> 3) % GRP;
    int b   = blk / (8 * GRP);
    int y0  = tyi * 8;

    __shared__ float s_in[8][12][68];
    __shared__ float s_wdw[200];
    __shared__ float s_wpw[64];

    int tid = threadIdx.x;
    if (tid < 200) s_wdw[tid] = w_dw[g * 200 + tid];
    else if (tid < 264) s_wpw[tid - 200] = w_pw[g * 64 + tid - 200];

    const float* inb = g_qkv + ((size_t)(b * OC3 + g * 8)) * HW_;
    for (int idx = tid; idx < 8 * 12 * 68; idx += 256) {
        int i   = idx / (12 * 68);
        int rem = idx - i * (12 * 68);
        int r   = rem / 68;
        int cx  = rem - r * 68;
        int y   = y0 + r - 2;
        int xx  = cx - 2;
        float v = 0.f;
        if ((unsigned)y < 64u && (unsigned)xx < 64u)
            v = inb[(size_t)i * HW_ + y * W_ + xx];
        s_in[i][r][cx] = v;
    }
    __syncthreads();

    #pragma unroll
    for (int pp = 0; pp < 2; pp++) {
        int px = tid + pp * 256;
        int yl = px >> 6;
        int x  = px & 63;
        float dwv[8];
        #pragma unroll
        for (int i = 0; i < 8; i++) {
            float s = 0.f;
            #pragma unroll
            for (int dy = 0; dy < 5; dy++)
                #pragma unroll
                for (int dx = 0; dx < 5; dx++)
                    s = fmaf(s_in[i][yl + dy][x + dx], s_wdw[i * 25 + dy * 5 + dx], s);
            dwv[i] = s;
        }
        size_t obase = ((size_t)(b * OC3 + g * 8)) * HW_ + (size_t)(y0 + yl) * W_ + x;
        #pragma unroll
        for (int o = 0; o < 8; o++) {
            float s = 0.f;
            #pragma unroll
            for (int i = 0; i < 8; i++) s = fmaf(s_wpw[o * 8 + i], dwv[i], s);
            g_agg[obase + (size_t)o * HW_] = s;
        }
    }
}

// ---------------- kv = sum_n relu(k)[d] * [v,1][e]  per (b,head) ------------
__global__ __launch_bounds__(256) void kv_kernel()
{
    int blk = blockIdx.x;
    int b = blk >> 6;
    int h = blk & 63;
    const float* kb = ms_ch(b, h * 24 + 8);

    float acc[8][9];
    #pragma unroll
    for (int d = 0; d < 8; d++)
        #pragma unroll
        for (int e = 0; e < 9; e++) acc[d][e] = 0.f;

    int tid = threadIdx.x;
    for (int p = tid; p < HW_; p += 256) {
        float kk[8], vv[8];
        #pragma unroll
        for (int d = 0; d < 8; d++) kk[d] = fmaxf(kb[(size_t)d * HW_ + p], 0.f);
        #pragma unroll
        for (int d = 0; d < 8; d++) vv[d] = kb[(size_t)(8 + d) * HW_ + p];
        #pragma unroll
        for (int d = 0; d < 8; d++) {
            #pragma unroll
            for (int e = 0; e < 8; e++) acc[d][e] = fmaf(kk[d], vv[e], acc[d][e]);
            acc[d][8] += kk[d];
        }
    }

    #pragma unroll
    for (int d = 0; d < 8; d++)
        #pragma unroll
        for (int e = 0; e < 9; e++)
            #pragma unroll
            for (int off = 16; off > 0; off >>= 1)
                acc[d][e] += __shfl_down_sync(0xffffffffu, acc[d][e], off);

    __shared__ float red[8][72];
    int warp = tid >> 5, lane = tid & 31;
    if (lane == 0) {
        #pragma unroll
        for (int d = 0; d < 8; d++)
            #pragma unroll
            for (int e = 0; e < 9; e++) red[warp][d * 9 + e] = acc[d][e];
    }
    __syncthreads();
    if (tid < 72) {
        float s = 0.f;
        #pragma unroll
        for (int w = 0; w < 8; w++) s += red[w][tid];
        g_kv[(size_t)blk * 72 + tid] = s;
    }
}

// ---------------------------------------------------------------------------
extern "C" void kernel_launch(void* const* d_in, const int* in_sizes, int n_in,
                              void* d_out, int out_size)
{
    const float* x      = (const float*)d_in[0];
    const float* w_qkv  = (const float*)d_in[1];
    const float* w_dw   = (const float*)d_in[2];
    const float* w_pw   = (const float*)d_in[3];
    const float* w_proj = (const float*)d_in[4];
    const float* gamma  = (const float*)d_in[5];
    const float* beta   = (const float*)d_in[6];
    const float* mean   = (const float*)d_in[7];
    const float* var    = (const float*)d_in[8];
    float* out = (float*)d_out;

    float* p_qkv;
    cudaGetSymbolAddress((void**)&p_qkv, g_qkv);

    // 1) qkv = w_qkv @ x   (M=768, K=256)
    gemm_kernel<256><<<dim3(256, 6), 256>>>(w_qkv, x, p_qkv);
    // 2) depthwise 5x5 + grouped pointwise -> agg
    dwpw_kernel<<<6144, 256>>>(w_dw, w_pw);
    // 3) per-head kv reduction
    kv_kernel<<<512, 256>>>();
    // 4) proj GEMM with on-the-fly attention + BN + residual
    proj_kernel<<<dim3(256, 2), 256>>>(w_proj, out, x, gamma, beta, mean, var);
}

// round 10
// speedup vs baseline: 1.5837x; 1.1584x over previous
#include <cuda_runtime.h>
#include <cuda_bf16.h>
#include <mma.h>
#include <cstdint>

using namespace nvcuda;

#define B_    8
#define C_    256
#define HW_   4096
#define W_    64
#define OC3   768
#define GRP   96
#define HEADS 64

// ------------------------- scratch (static device memory) -------------------
__device__ float g_qkv[(size_t)B_ * OC3 * HW_];
__device__ float g_agg[(size_t)B_ * OC3 * HW_];
__device__ float g_kv [(size_t)B_ * HEADS * 72];

__device__ __forceinline__ const float* ms_ch(int b, int c) {
    return (c < OC3) ? (g_qkv + ((size_t)(b * OC3 + c)) * HW_)
                     : (g_agg + ((size_t)(b * OC3 + (c - OC3))) * HW_);
}

// split a float pair into bf16 hi / lo pairs
__device__ __forceinline__ void bsplit2(float x, float y,
                                        __nv_bfloat162& hi, __nv_bfloat162& lo)
{
    __nv_bfloat16 hx = __float2bfloat16(x);
    __nv_bfloat16 hy = __float2bfloat16(y);
    __nv_bfloat16 lx = __float2bfloat16(x - __bfloat162float(hx));
    __nv_bfloat16 ly = __float2bfloat16(y - __bfloat162float(hy));
    hi = __halves2bfloat162(hx, hy);
    lo = __halves2bfloat162(lx, ly);
}

// ------------------- qkv GEMM via wmma bf16-split ---------------------------
// C[b,m,p] = sum_k W[m,k] * x[b,k,p].  M=768, K=256.
// CTA: 128(m) x 128(p); 8 warps, each 32(m) x 64(p).
// 3-term split: W*X ~= Whi*Xhi + Whi*Xlo + Wlo*Xhi  (f32 accumulate).
__global__ __launch_bounds__(256, 2) void qkv_wmma_kernel(
    const float* __restrict__ A, const float* __restrict__ Bm,
    float* __restrict__ Cm)
{
    constexpr int KDIM = 256;
    __shared__ __nv_bfloat16 sAhi[128][24];   // [m][k], pad to 24
    __shared__ __nv_bfloat16 sAlo[128][24];
    __shared__ __nv_bfloat16 sBhi[16][136];   // [k][p], pad to 136
    __shared__ __nv_bfloat16 sBlo[16][136];

    const int m0 = blockIdx.y * 128;
    const int n0 = blockIdx.x * 128;
    const int b  = n0 >> 12;
    const int p0 = n0 & 4095;
    const int tid = threadIdx.x;
    const int wid = tid >> 5;
    const int wy = wid >> 1;      // 0..3 -> m offset wy*32
    const int wx = wid & 1;       // 0..1 -> p offset wx*64

    wmma::fragment<wmma::accumulator, 16, 16, 16, float> acc[2][4];
    #pragma unroll
    for (int mi = 0; mi < 2; mi++)
        #pragma unroll
        for (int pi = 0; pi < 4; pi++)
            wmma::fill_fragment(acc[mi][pi], 0.0f);

    const float* Bbase = Bm + (size_t)b * KDIM * HW_ + p0;

    for (int k0 = 0; k0 < KDIM; k0 += 16) {
        // A slab: 128 x 16, convert to hi/lo
        #pragma unroll
        for (int it = 0; it < 2; it++) {
            int lin = tid + it * 256;
            int m  = lin >> 2;
            int kq = (lin & 3) * 4;
            float4 v = *(const float4*)(A + (size_t)(m0 + m) * KDIM + k0 + kq);
            __nv_bfloat162 h0, l0, h1, l1;
            bsplit2(v.x, v.y, h0, l0);
            bsplit2(v.z, v.w, h1, l1);
            *(__nv_bfloat162*)&sAhi[m][kq]     = h0;
            *(__nv_bfloat162*)&sAhi[m][kq + 2] = h1;
            *(__nv_bfloat162*)&sAlo[m][kq]     = l0;
            *(__nv_bfloat162*)&sAlo[m][kq + 2] = l1;
        }
        // B slab: 16 x 128, convert to hi/lo
        #pragma unroll
        for (int it = 0; it < 2; it++) {
            int lin = tid + it * 256;
            int kr = lin >> 5;
            int pq = (lin & 31) * 4;
            float4 v = *(const float4*)(Bbase + (size_t)(k0 + kr) * HW_ + pq);
            __nv_bfloat162 h0, l0, h1, l1;
            bsplit2(v.x, v.y, h0, l0);
            bsplit2(v.z, v.w, h1, l1);
            *(__nv_bfloat162*)&sBhi[kr][pq]     = h0;
            *(__nv_bfloat162*)&sBhi[kr][pq + 2] = h1;
            *(__nv_bfloat162*)&sBlo[kr][pq]     = l0;
            *(__nv_bfloat162*)&sBlo[kr][pq + 2] = l1;
        }
        __syncthreads();

        wmma::fragment<wmma::matrix_a, 16, 16, 16, __nv_bfloat16, wmma::row_major> ahi[2], alo[2];
        #pragma unroll
        for (int mi = 0; mi < 2; mi++) {
            wmma::load_matrix_sync(ahi[mi], &sAhi[wy * 32 + mi * 16][0], 24);
            wmma::load_matrix_sync(alo[mi], &sAlo[wy * 32 + mi * 16][0], 24);
        }
        #pragma unroll
        for (int pi = 0; pi < 4; pi++) {
            wmma::fragment<wmma::matrix_b, 16, 16, 16, __nv_bfloat16, wmma::row_major> bhi, blo;
            wmma::load_matrix_sync(bhi, &sBhi[0][wx * 64 + pi * 16], 136);
            wmma::load_matrix_sync(blo, &sBlo[0][wx * 64 + pi * 16], 136);
            #pragma unroll
            for (int mi = 0; mi < 2; mi++) {
                wmma::mma_sync(acc[mi][pi], ahi[mi], bhi, acc[mi][pi]);
                wmma::mma_sync(acc[mi][pi], ahi[mi], blo, acc[mi][pi]);
                wmma::mma_sync(acc[mi][pi], alo[mi], bhi, acc[mi][pi]);
            }
        }
        __syncthreads();
    }

    const size_t cb = (size_t)b * OC3 * HW_;
    #pragma unroll
    for (int mi = 0; mi < 2; mi++)
        #pragma unroll
        for (int pi = 0; pi < 4; pi++) {
            float* cp = Cm + cb + (size_t)(m0 + wy * 32 + mi * 16) * HW_
                        + p0 + wx * 64 + pi * 16;
            wmma::store_matrix_sync(cp, acc[mi][pi], HW_, wmma::mem_row_major);
        }
}

// ---------------- fused proj GEMM: out = x + BN(w_proj @ att) ---------------
// R9 version (known good): att rows on the fly + fragment double-buffer.
__global__ __launch_bounds__(256, 2) void proj_kernel(
    const float* __restrict__ A, float* __restrict__ Cm,
    const float* __restrict__ xres,
    const float* __restrict__ gamma, const float* __restrict__ beta,
    const float* __restrict__ mean, const float* __restrict__ var)
{
    __shared__ float As[16][132];
    __shared__ float Bs[16][128];
    __shared__ float kvs[HEADS * 72];
    __shared__ float s_inv[128];
    __shared__ float s_bias[128];

    const int m0 = blockIdx.y * 128;
    const int n0 = blockIdx.x * 128;
    const int b  = n0 >> 12;
    const int p0 = n0 & 4095;
    const int tid = threadIdx.x;
    const int tx = tid & 15;
    const int ty = tid >> 4;

    if (tid < 128) {
        int c = m0 + tid;
        float iv = gamma[c] * rsqrtf(var[c] + 1e-6f);
        s_inv[tid]  = iv;
        s_bias[tid] = beta[c] - mean[c] * iv;
    }
    for (int i = tid; i < HEADS * 72; i += 256)
        kvs[i] = g_kv[(size_t)b * HEADS * 72 + i];
    __syncthreads();

    float acc[8][8];
    #pragma unroll
    for (int i = 0; i < 8; i++)
        #pragma unroll
        for (int j = 0; j < 8; j++) acc[i][j] = 0.f;

    const int hh = tid >> 7;
    const int px = tid & 127;

    for (int k0 = 0; k0 < 512; k0 += 16) {
        #pragma unroll
        for (int it = 0; it < 2; it++) {
            int lin = tid + it * 256;
            int m  = lin >> 2;
            int c4 = (lin & 3) * 4;
            float4 v = *(const float4*)(A + (size_t)(m0 + m) * 512 + k0 + c4);
            As[c4 + 0][m] = v.x; As[c4 + 1][m] = v.y;
            As[c4 + 2][m] = v.z; As[c4 + 3][m] = v.w;
        }
        {
            int h = (k0 >> 3) + hh;
            const float* qb = ms_ch(b, h * 24);
            const float* kvp = &kvs[h * 72];
            float q[8];
            #pragma unroll
            for (int d = 0; d < 8; d++)
                q[d] = fmaxf(qb[(size_t)d * HW_ + p0 + px], 0.f);
            float den = 0.f;
            #pragma unroll
            for (int d = 0; d < 8; d++) den = fmaf(q[d], kvp[d * 9 + 8], den);
            float r = 1.f / (den + 1e-15f);
            #pragma unroll
            for (int e = 0; e < 8; e++) {
                float s = 0.f;
                #pragma unroll
                for (int d = 0; d < 8; d++) s = fmaf(q[d], kvp[d * 9 + e], s);
                Bs[hh * 8 + e][px] = s * r;
            }
        }
        __syncthreads();

        float af[2][8], bf[2][8];
        *(float4*)&af[0][0] = *(const float4*)&As[0][ty * 4];
        *(float4*)&af[0][4] = *(const float4*)&As[0][ty * 4 + 64];
        *(float4*)&bf[0][0] = *(const float4*)&Bs[0][tx * 4];
        *(float4*)&bf[0][4] = *(const float4*)&Bs[0][tx * 4 + 64];
        #pragma unroll
        for (int kk = 0; kk < 16; kk++) {
            const int c = kk & 1, n = c ^ 1;
            if (kk < 15) {
                *(float4*)&af[n][0] = *(const float4*)&As[kk + 1][ty * 4];
                *(float4*)&af[n][4] = *(const float4*)&As[kk + 1][ty * 4 + 64];
                *(float4*)&bf[n][0] = *(const float4*)&Bs[kk + 1][tx * 4];
                *(float4*)&bf[n][4] = *(const float4*)&Bs[kk + 1][tx * 4 + 64];
            }
            #pragma unroll
            for (int i = 0; i < 8; i++)
                #pragma unroll
                for (int j = 0; j < 8; j++)
                    acc[i][j] = fmaf(af[c][i], bf[c][j], acc[i][j]);
        }
        __syncthreads();
    }

    const size_t cb = (size_t)b * 256 * HW_;
    #pragma unroll
    for (int i = 0; i < 8; i++) {
        int mi = ty * 4 + (i < 4 ? i : 60 + i);
        size_t rowoff = cb + (size_t)(m0 + mi) * HW_ + p0;
        float4 v0 = make_float4(acc[i][0], acc[i][1], acc[i][2], acc[i][3]);
        float4 v1 = make_float4(acc[i][4], acc[i][5], acc[i][6], acc[i][7]);
        float iv = s_inv[mi], bb = s_bias[mi];
        float4 x0 = *(const float4*)(xres + rowoff + tx * 4);
        float4 x1 = *(const float4*)(xres + rowoff + tx * 4 + 64);
        v0.x = fmaf(v0.x, iv, bb) + x0.x;  v0.y = fmaf(v0.y, iv, bb) + x0.y;
        v0.z = fmaf(v0.z, iv, bb) + x0.z;  v0.w = fmaf(v0.w, iv, bb) + x0.w;
        v1.x = fmaf(v1.x, iv, bb) + x1.x;  v1.y = fmaf(v1.y, iv, bb) + x1.y;
        v1.z = fmaf(v1.z, iv, bb) + x1.z;  v1.w = fmaf(v1.w, iv, bb) + x1.w;
        *(float4*)(Cm + rowoff + tx * 4)      = v0;
        *(float4*)(Cm + rowoff + tx * 4 + 64) = v1;
    }
}

// ---------------- fused depthwise 5x5 + grouped pointwise 8x8 ---------------
__global__ __launch_bounds__(256) void dwpw_kernel(
    const float* __restrict__ w_dw, const float* __restrict__ w_pw)
{
    int blk = blockIdx.x;
    int tyi = blk & 7;
    int g   = (blk >> 3) % GRP;
    int b   = blk / (8 * GRP);
    int y0  = tyi * 8;

    __shared__ float s_in[8][12][68];
    __shared__ float s_wdw[200];
    __shared__ float s_wpw[64];

    int tid = threadIdx.x;
    if (tid < 200) s_wdw[tid] = w_dw[g * 200 + tid];
    else if (tid < 264) s_wpw[tid - 200] = w_pw[g * 64 + tid - 200];

    const float* inb = g_qkv + ((size_t)(b * OC3 + g * 8)) * HW_;
    for (int idx = tid; idx < 8 * 12 * 68; idx += 256) {
        int i   = idx / (12 * 68);
        int rem = idx - i * (12 * 68);
        int r   = rem / 68;
        int cx  = rem - r * 68;
        int y   = y0 + r - 2;
        int xx  = cx - 2;
        float v = 0.f;
        if ((unsigned)y < 64u && (unsigned)xx < 64u)
            v = inb[(size_t)i * HW_ + y * W_ + xx];
        s_in[i][r][cx] = v;
    }
    __syncthreads();

    #pragma unroll
    for (int pp = 0; pp < 2; pp++) {
        int px = tid + pp * 256;
        int yl = px >> 6;
        int x  = px & 63;
        float dwv[8];
        #pragma unroll
        for (int i = 0; i < 8; i++) {
            float s = 0.f;
            #pragma unroll
            for (int dy = 0; dy < 5; dy++)
                #pragma unroll
                for (int dx = 0; dx < 5; dx++)
                    s = fmaf(s_in[i][yl + dy][x + dx], s_wdw[i * 25 + dy * 5 + dx], s);
            dwv[i] = s;
        }
        size_t obase = ((size_t)(b * OC3 + g * 8)) * HW_ + (size_t)(y0 + yl) * W_ + x;
        #pragma unroll
        for (int o = 0; o < 8; o++) {
            float s = 0.f;
            #pragma unroll
            for (int i = 0; i < 8; i++) s = fmaf(s_wpw[o * 8 + i], dwv[i], s);
            g_agg[obase + (size_t)o * HW_] = s;
        }
    }
}

// ---------------- kv = sum_n relu(k)[d] * [v,1][e]  per (b,head) ------------
__global__ __launch_bounds__(256) void kv_kernel()
{
    int blk = blockIdx.x;
    int b = blk >> 6;
    int h = blk & 63;
    const float* kb = ms_ch(b, h * 24 + 8);

    float acc[8][9];
    #pragma unroll
    for (int d = 0; d < 8; d++)
        #pragma unroll
        for (int e = 0; e < 9; e++) acc[d][e] = 0.f;

    int tid = threadIdx.x;
    for (int p = tid; p < HW_; p += 256) {
        float kk[8], vv[8];
        #pragma unroll
        for (int d = 0; d < 8; d++) kk[d] = fmaxf(kb[(size_t)d * HW_ + p], 0.f);
        #pragma unroll
        for (int d = 0; d < 8; d++) vv[d] = kb[(size_t)(8 + d) * HW_ + p];
        #pragma unroll
        for (int d = 0; d < 8; d++) {
            #pragma unroll
            for (int e = 0; e < 8; e++) acc[d][e] = fmaf(kk[d], vv[e], acc[d][e]);
            acc[d][8] += kk[d];
        }
    }

    #pragma unroll
    for (int d = 0; d < 8; d++)
        #pragma unroll
        for (int e = 0; e < 9; e++)
            #pragma unroll
            for (int off = 16; off > 0; off >>= 1)
                acc[d][e] += __shfl_down_sync(0xffffffffu, acc[d][e], off);

    __shared__ float red[8][72];
    int warp = tid >> 5, lane = tid & 31;
    if (lane == 0) {
        #pragma unroll
        for (int d = 0; d < 8; d++)
            #pragma unroll
            for (int e = 0; e < 9; e++) red[warp][d * 9 + e] = acc[d][e];
    }
    __syncthreads();
    if (tid < 72) {
        float s = 0.f;
        #pragma unroll
        for (int w = 0; w < 8; w++) s += red[w][tid];
        g_kv[(size_t)blk * 72 + tid] = s;
    }
}

// ---------------------------------------------------------------------------
extern "C" void kernel_launch(void* const* d_in, const int* in_sizes, int n_in,
                              void* d_out, int out_size)
{
    const float* x      = (const float*)d_in[0];
    const float* w_qkv  = (const float*)d_in[1];
    const float* w_dw   = (const float*)d_in[2];
    const float* w_pw   = (const float*)d_in[3];
    const float* w_proj = (const float*)d_in[4];
    const float* gamma  = (const float*)d_in[5];
    const float* beta   = (const float*)d_in[6];
    const float* mean   = (const float*)d_in[7];
    const float* var    = (const float*)d_in[8];
    float* out = (float*)d_out;

    float* p_qkv;
    cudaGetSymbolAddress((void**)&p_qkv, g_qkv);

    // 1) qkv = w_qkv @ x  (M=768, K=256) — wmma bf16-split tensor-core GEMM
    qkv_wmma_kernel<<<dim3(256, 6), 256>>>(w_qkv, x, p_qkv);
    // 2) depthwise 5x5 + grouped pointwise -> agg
    dwpw_kernel<<<6144, 256>>>(w_dw, w_pw);
    // 3) per-head kv reduction
    kv_kernel<<<512, 256>>>();
    // 4) proj GEMM with on-the-fly attention + BN + residual
    proj_kernel<<<dim3(256, 2), 256>>>(w_proj, out, x, gamma, beta, mean, var);
}

// round 11
// speedup vs baseline: 1.7544x; 1.1077x over previous
#include <cuda_runtime.h>
#include <cuda_bf16.h>
#include <mma.h>
#include <cstdint>

using namespace nvcuda;

#define B_    8
#define C_    256
#define HW_   4096
#define W_    64
#define OC3   768
#define GRP   96
#define HEADS 64

// ------------------------- scratch (static device memory) -------------------
__device__ float g_qkv[(size_t)B_ * OC3 * HW_];
__device__ float g_agg[(size_t)B_ * OC3 * HW_];
__device__ float g_kv [(size_t)B_ * HEADS * 72];

__device__ __forceinline__ const float* ms_ch(int b, int c) {
    return (c < OC3) ? (g_qkv + ((size_t)(b * OC3 + c)) * HW_)
                     : (g_agg + ((size_t)(b * OC3 + (c - OC3))) * HW_);
}

// split a float pair into bf16 hi / lo pairs
__device__ __forceinline__ void bsplit2(float x, float y,
                                        __nv_bfloat162& hi, __nv_bfloat162& lo)
{
    __nv_bfloat16 hx = __float2bfloat16(x);
    __nv_bfloat16 hy = __float2bfloat16(y);
    __nv_bfloat16 lx = __float2bfloat16(x - __bfloat162float(hx));
    __nv_bfloat16 ly = __float2bfloat16(y - __bfloat162float(hy));
    hi = __halves2bfloat162(hx, hy);
    lo = __halves2bfloat162(lx, ly);
}
__device__ __forceinline__ void bsplit1(float x, __nv_bfloat16& hi, __nv_bfloat16& lo)
{
    hi = __float2bfloat16(x);
    lo = __float2bfloat16(x - __bfloat162float(hi));
}

// ------------------- qkv GEMM via wmma bf16-split (R10, known good) ---------
__global__ __launch_bounds__(256, 2) void qkv_wmma_kernel(
    const float* __restrict__ A, const float* __restrict__ Bm,
    float* __restrict__ Cm)
{
    constexpr int KDIM = 256;
    __shared__ __nv_bfloat16 sAhi[128][24];
    __shared__ __nv_bfloat16 sAlo[128][24];
    __shared__ __nv_bfloat16 sBhi[16][136];
    __shared__ __nv_bfloat16 sBlo[16][136];

    const int m0 = blockIdx.y * 128;
    const int n0 = blockIdx.x * 128;
    const int b  = n0 >> 12;
    const int p0 = n0 & 4095;
    const int tid = threadIdx.x;
    const int wid = tid >> 5;
    const int wy = wid >> 1;
    const int wx = wid & 1;

    wmma::fragment<wmma::accumulator, 16, 16, 16, float> acc[2][4];
    #pragma unroll
    for (int mi = 0; mi < 2; mi++)
        #pragma unroll
        for (int pi = 0; pi < 4; pi++)
            wmma::fill_fragment(acc[mi][pi], 0.0f);

    const float* Bbase = Bm + (size_t)b * KDIM * HW_ + p0;

    for (int k0 = 0; k0 < KDIM; k0 += 16) {
        #pragma unroll
        for (int it = 0; it < 2; it++) {
            int lin = tid + it * 256;
            int m  = lin >> 2;
            int kq = (lin & 3) * 4;
            float4 v = *(const float4*)(A + (size_t)(m0 + m) * KDIM + k0 + kq);
            __nv_bfloat162 h0, l0, h1, l1;
            bsplit2(v.x, v.y, h0, l0);
            bsplit2(v.z, v.w, h1, l1);
            *(__nv_bfloat162*)&sAhi[m][kq]     = h0;
            *(__nv_bfloat162*)&sAhi[m][kq + 2] = h1;
            *(__nv_bfloat162*)&sAlo[m][kq]     = l0;
            *(__nv_bfloat162*)&sAlo[m][kq + 2] = l1;
        }
        #pragma unroll
        for (int it = 0; it < 2; it++) {
            int lin = tid + it * 256;
            int kr = lin >> 5;
            int pq = (lin & 31) * 4;
            float4 v = *(const float4*)(Bbase + (size_t)(k0 + kr) * HW_ + pq);
            __nv_bfloat162 h0, l0, h1, l1;
            bsplit2(v.x, v.y, h0, l0);
            bsplit2(v.z, v.w, h1, l1);
            *(__nv_bfloat162*)&sBhi[kr][pq]     = h0;
            *(__nv_bfloat162*)&sBhi[kr][pq + 2] = h1;
            *(__nv_bfloat162*)&sBlo[kr][pq]     = l0;
            *(__nv_bfloat162*)&sBlo[kr][pq + 2] = l1;
        }
        __syncthreads();

        wmma::fragment<wmma::matrix_a, 16, 16, 16, __nv_bfloat16, wmma::row_major> ahi[2], alo[2];
        #pragma unroll
        for (int mi = 0; mi < 2; mi++) {
            wmma::load_matrix_sync(ahi[mi], &sAhi[wy * 32 + mi * 16][0], 24);
            wmma::load_matrix_sync(alo[mi], &sAlo[wy * 32 + mi * 16][0], 24);
        }
        #pragma unroll
        for (int pi = 0; pi < 4; pi++) {
            wmma::fragment<wmma::matrix_b, 16, 16, 16, __nv_bfloat16, wmma::row_major> bhi, blo;
            wmma::load_matrix_sync(bhi, &sBhi[0][wx * 64 + pi * 16], 136);
            wmma::load_matrix_sync(blo, &sBlo[0][wx * 64 + pi * 16], 136);
            #pragma unroll
            for (int mi = 0; mi < 2; mi++) {
                wmma::mma_sync(acc[mi][pi], ahi[mi], bhi, acc[mi][pi]);
                wmma::mma_sync(acc[mi][pi], ahi[mi], blo, acc[mi][pi]);
                wmma::mma_sync(acc[mi][pi], alo[mi], bhi, acc[mi][pi]);
            }
        }
        __syncthreads();
    }

    const size_t cb = (size_t)b * OC3 * HW_;
    #pragma unroll
    for (int mi = 0; mi < 2; mi++)
        #pragma unroll
        for (int pi = 0; pi < 4; pi++) {
            float* cp = Cm + cb + (size_t)(m0 + wy * 32 + mi * 16) * HW_
                        + p0 + wx * 64 + pi * 16;
            wmma::store_matrix_sync(cp, acc[mi][pi], HW_, wmma::mem_row_major);
        }
}

// ---------- proj GEMM via wmma bf16-split, att fused, BN + residual ---------
// out[b,m,p] = x + BN( sum_k w_proj[m,k] * att[b,k,p] ), M=256, K=512.
// att rows (16 per slab = 2 heads x 8 e) computed in f32 then split to bf16.
__global__ __launch_bounds__(256, 2) void proj_wmma_kernel(
    const float* __restrict__ A, float* __restrict__ Cm,
    const float* __restrict__ xres,
    const float* __restrict__ gamma, const float* __restrict__ beta,
    const float* __restrict__ mean, const float* __restrict__ var)
{
    constexpr int KDIM = 512;
    __shared__ __nv_bfloat16 sAhi[128][24];
    __shared__ __nv_bfloat16 sAlo[128][24];
    __shared__ __nv_bfloat16 sBhi[16][136];
    __shared__ __nv_bfloat16 sBlo[16][136];
    __shared__ float kvs[HEADS * 72];
    __shared__ float s_inv[128];
    __shared__ float s_bias[128];
    __shared__ float stage[8][256];

    const int m0 = blockIdx.y * 128;
    const int n0 = blockIdx.x * 128;
    const int b  = n0 >> 12;
    const int p0 = n0 & 4095;
    const int tid = threadIdx.x;
    const int wid = tid >> 5;
    const int lane = tid & 31;
    const int wy = wid >> 1;
    const int wx = wid & 1;

    if (tid < 128) {
        int c = m0 + tid;
        float iv = gamma[c] * rsqrtf(var[c] + 1e-6f);
        s_inv[tid]  = iv;
        s_bias[tid] = beta[c] - mean[c] * iv;
    }
    for (int i = tid; i < HEADS * 72; i += 256)
        kvs[i] = g_kv[(size_t)b * HEADS * 72 + i];
    __syncthreads();

    wmma::fragment<wmma::accumulator, 16, 16, 16, float> acc[2][4];
    #pragma unroll
    for (int mi = 0; mi < 2; mi++)
        #pragma unroll
        for (int pi = 0; pi < 4; pi++)
            wmma::fill_fragment(acc[mi][pi], 0.0f);

    const int hh = tid >> 7;       // which of the 2 heads in this slab
    const int px = tid & 127;      // pixel column within tile

    for (int k0 = 0; k0 < KDIM; k0 += 16) {
        // A slab (w_proj 128 x 16) -> bf16 hi/lo
        #pragma unroll
        for (int it = 0; it < 2; it++) {
            int lin = tid + it * 256;
            int m  = lin >> 2;
            int kq = (lin & 3) * 4;
            float4 v = *(const float4*)(A + (size_t)(m0 + m) * KDIM + k0 + kq);
            __nv_bfloat162 h0, l0, h1, l1;
            bsplit2(v.x, v.y, h0, l0);
            bsplit2(v.z, v.w, h1, l1);
            *(__nv_bfloat162*)&sAhi[m][kq]     = h0;
            *(__nv_bfloat162*)&sAhi[m][kq + 2] = h1;
            *(__nv_bfloat162*)&sAlo[m][kq]     = l0;
            *(__nv_bfloat162*)&sAlo[m][kq + 2] = l1;
        }
        // B slab: att rows for heads (k0>>3)+hh, e = 0..7, f32 -> bf16 hi/lo
        {
            int h = (k0 >> 3) + hh;
            const float* qb = ms_ch(b, h * 24);
            const float* kvp = &kvs[h * 72];
            float q[8];
            #pragma unroll
            for (int d = 0; d < 8; d++)
                q[d] = fmaxf(qb[(size_t)d * HW_ + p0 + px], 0.f);
            float den = 0.f;
            #pragma unroll
            for (int d = 0; d < 8; d++) den = fmaf(q[d], kvp[d * 9 + 8], den);
            float r = 1.f / (den + 1e-15f);
            #pragma unroll
            for (int e = 0; e < 8; e++) {
                float s = 0.f;
                #pragma unroll
                for (int d = 0; d < 8; d++) s = fmaf(q[d], kvp[d * 9 + e], s);
                __nv_bfloat16 hi, lo;
                bsplit1(s * r, hi, lo);
                sBhi[hh * 8 + e][px] = hi;
                sBlo[hh * 8 + e][px] = lo;
            }
        }
        __syncthreads();

        wmma::fragment<wmma::matrix_a, 16, 16, 16, __nv_bfloat16, wmma::row_major> ahi[2], alo[2];
        #pragma unroll
        for (int mi = 0; mi < 2; mi++) {
            wmma::load_matrix_sync(ahi[mi], &sAhi[wy * 32 + mi * 16][0], 24);
            wmma::load_matrix_sync(alo[mi], &sAlo[wy * 32 + mi * 16][0], 24);
        }
        #pragma unroll
        for (int pi = 0; pi < 4; pi++) {
            wmma::fragment<wmma::matrix_b, 16, 16, 16, __nv_bfloat16, wmma::row_major> bhi, blo;
            wmma::load_matrix_sync(bhi, &sBhi[0][wx * 64 + pi * 16], 136);
            wmma::load_matrix_sync(blo, &sBlo[0][wx * 64 + pi * 16], 136);
            #pragma unroll
            for (int mi = 0; mi < 2; mi++) {
                wmma::mma_sync(acc[mi][pi], ahi[mi], bhi, acc[mi][pi]);
                wmma::mma_sync(acc[mi][pi], ahi[mi], blo, acc[mi][pi]);
                wmma::mma_sync(acc[mi][pi], alo[mi], bhi, acc[mi][pi]);
            }
        }
        __syncthreads();
    }

    // epilogue: stage each 16x16 tile, apply BN + residual, write out
    const size_t cb = (size_t)b * 256 * HW_;
    #pragma unroll
    for (int mi = 0; mi < 2; mi++)
        #pragma unroll
        for (int pi = 0; pi < 4; pi++) {
            wmma::store_matrix_sync(&stage[wid][0], acc[mi][pi], 16, wmma::mem_row_major);
            __syncwarp();
            const int mloc0 = wy * 32 + mi * 16;
            const int pcol0 = p0 + wx * 64 + pi * 16;
            // each lane: 8 contiguous elements (half a row)
            int idx = lane * 8;
            int r = idx >> 4;
            int c = idx & 15;
            int mloc = mloc0 + r;
            size_t go = cb + (size_t)(m0 + mloc) * HW_ + pcol0 + c;
            float iv = s_inv[mloc], bb = s_bias[mloc];
            float4 x0 = *(const float4*)(xres + go);
            float4 x1 = *(const float4*)(xres + go + 4);
            float* sp = &stage[wid][idx];
            float4 v0 = make_float4(
                fmaf(sp[0], iv, bb) + x0.x, fmaf(sp[1], iv, bb) + x0.y,
                fmaf(sp[2], iv, bb) + x0.z, fmaf(sp[3], iv, bb) + x0.w);
            float4 v1 = make_float4(
                fmaf(sp[4], iv, bb) + x1.x, fmaf(sp[5], iv, bb) + x1.y,
                fmaf(sp[6], iv, bb) + x1.z, fmaf(sp[7], iv, bb) + x1.w);
            *(float4*)(Cm + go)     = v0;
            *(float4*)(Cm + go + 4) = v1;
            __syncwarp();
        }
}

// ---------------- fused depthwise 5x5 + grouped pointwise 8x8 ---------------
__global__ __launch_bounds__(256) void dwpw_kernel(
    const float* __restrict__ w_dw, const float* __restrict__ w_pw)
{
    int blk = blockIdx.x;
    int tyi = blk & 7;
    int g   = (blk >> 3) % GRP;
    int b   = blk / (8 * GRP);
    int y0  = tyi * 8;

    __shared__ float s_in[8][12][68];
    __shared__ float s_wdw[200];
    __shared__ float s_wpw[64];

    int tid = threadIdx.x;
    if (tid < 200) s_wdw[tid] = w_dw[g * 200 + tid];
    else if (tid < 264) s_wpw[tid - 200] = w_pw[g * 64 + tid - 200];

    const float* inb = g_qkv + ((size_t)(b * OC3 + g * 8)) * HW_;
    for (int idx = tid; idx < 8 * 12 * 68; idx += 256) {
        int i   = idx / (12 * 68);
        int rem = idx - i * (12 * 68);
        int r   = rem / 68;
        int cx  = rem - r * 68;
        int y   = y0 + r - 2;
        int xx  = cx - 2;
        float v = 0.f;
        if ((unsigned)y < 64u && (unsigned)xx < 64u)
            v = inb[(size_t)i * HW_ + y * W_ + xx];
        s_in[i][r][cx] = v;
    }
    __syncthreads();

    #pragma unroll
    for (int pp = 0; pp < 2; pp++) {
        int px = tid + pp * 256;
        int yl = px >> 6;
        int x  = px & 63;
        float dwv[8];
        #pragma unroll
        for (int i = 0; i < 8; i++) {
            float s = 0.f;
            #pragma unroll
            for (int dy = 0; dy < 5; dy++)
                #pragma unroll
                for (int dx = 0; dx < 5; dx++)
                    s = fmaf(s_in[i][yl + dy][x + dx], s_wdw[i * 25 + dy * 5 + dx], s);
            dwv[i] = s;
        }
        size_t obase = ((size_t)(b * OC3 + g * 8)) * HW_ + (size_t)(y0 + yl) * W_ + x;
        #pragma unroll
        for (int o = 0; o < 8; o++) {
            float s = 0.f;
            #pragma unroll
            for (int i = 0; i < 8; i++) s = fmaf(s_wpw[o * 8 + i], dwv[i], s);
            g_agg[obase + (size_t)o * HW_] = s;
        }
    }
}

// ---------------- kv = sum_n relu(k)[d] * [v,1][e]  per (b,head) ------------
__global__ __launch_bounds__(256) void kv_kernel()
{
    int blk = blockIdx.x;
    int b = blk >> 6;
    int h = blk & 63;
    const float* kb = ms_ch(b, h * 24 + 8);

    float acc[8][9];
    #pragma unroll
    for (int d = 0; d < 8; d++)
        #pragma unroll
        for (int e = 0; e < 9; e++) acc[d][e] = 0.f;

    int tid = threadIdx.x;
    for (int p = tid; p < HW_; p += 256) {
        float kk[8], vv[8];
        #pragma unroll
        for (int d = 0; d < 8; d++) kk[d] = fmaxf(kb[(size_t)d * HW_ + p], 0.f);
        #pragma unroll
        for (int d = 0; d < 8; d++) vv[d] = kb[(size_t)(8 + d) * HW_ + p];
        #pragma unroll
        for (int d = 0; d < 8; d++) {
            #pragma unroll
            for (int e = 0; e < 8; e++) acc[d][e] = fmaf(kk[d], vv[e], acc[d][e]);
            acc[d][8] += kk[d];
        }
    }

    #pragma unroll
    for (int d = 0; d < 8; d++)
        #pragma unroll
        for (int e = 0; e < 9; e++)
            #pragma unroll
            for (int off = 16; off > 0; off >>= 1)
                acc[d][e] += __shfl_down_sync(0xffffffffu, acc[d][e], off);

    __shared__ float red[8][72];
    int warp = tid >> 5, lane = tid & 31;
    if (lane == 0) {
        #pragma unroll
        for (int d = 0; d < 8; d++)
            #pragma unroll
            for (int e = 0; e < 9; e++) red[warp][d * 9 + e] = acc[d][e];
    }
    __syncthreads();
    if (tid < 72) {
        float s = 0.f;
        #pragma unroll
        for (int w = 0; w < 8; w++) s += red[w][tid];
        g_kv[(size_t)blk * 72 + tid] = s;
    }
}

// ---------------------------------------------------------------------------
extern "C" void kernel_launch(void* const* d_in, const int* in_sizes, int n_in,
                              void* d_out, int out_size)
{
    const float* x      = (const float*)d_in[0];
    const float* w_qkv  = (const float*)d_in[1];
    const float* w_dw   = (const float*)d_in[2];
    const float* w_pw   = (const float*)d_in[3];
    const float* w_proj = (const float*)d_in[4];
    const float* gamma  = (const float*)d_in[5];
    const float* beta   = (const float*)d_in[6];
    const float* mean   = (const float*)d_in[7];
    const float* var    = (const float*)d_in[8];
    float* out = (float*)d_out;

    float* p_qkv;
    cudaGetSymbolAddress((void**)&p_qkv, g_qkv);

    // 1) qkv = w_qkv @ x  (M=768, K=256) — wmma bf16-split
    qkv_wmma_kernel<<<dim3(256, 6), 256>>>(w_qkv, x, p_qkv);
    // 2) depthwise 5x5 + grouped pointwise -> agg
    dwpw_kernel<<<6144, 256>>>(w_dw, w_pw);
    // 3) per-head kv reduction
    kv_kernel<<<512, 256>>>();
    // 4) proj GEMM (wmma bf16-split) with fused attention + BN + residual
    proj_wmma_kernel<<<dim3(256, 2), 256>>>(w_proj, out, x, gamma, beta, mean, var);
}